// round 8
// baseline (speedup 1.0000x reference)
#include <cuda_runtime.h>
#include <math_constants.h>

#define BB 8
#define NN 4096
#define NS 1024
#define THREADS 512
#define TOPK 4
#define EMPTY (-1)

// Per-batch loss scratch (no device allocation allowed).
__device__ float g_batchLoss[BB];

// rowKey: [63:32] d2 bits  [31:16] row id  [15:0] col id  (lexmin == reference order)
// INVARIANT (after init / each iteration): for every alive row, rowKey holds the
// TRUE min over alive cols with the lowest achieving col; dead rows = ~0ULL.
// rowTop entries: [41:10] d2 bits  [9:0] col id, ascending; ~0ULL = invalid.
#define MKKEY(vb, rid, cs) ((((unsigned long long)(vb)) << 32) | \
                            ((unsigned)(rid) << 16) | (unsigned)(cs))

struct SmemLayout {
    float4 p1s[NS];                      // 16 KB  S1 points by row id
    float4 p2sC[NS];                     // 16 KB  S2 points, COMPACT; .w = col id
    unsigned long long rowKey[NS];       //  8 KB  valid best key (~0 = dead row)
    unsigned long long rowTop[NS*TOPK];  // 32 KB  top-4 packed (d2<<10|col), sorted
    int head[NS];                        //  4 KB  col -> first row pointing at it
    int nxt[NS];                         //  4 KB  row -> next row in same col list
    unsigned short colPos[NS];           //  2 KB  col id -> compact pos
    unsigned char  colAlive[NS];         //  1 KB
};
#define SMEM_BYTES ((int)sizeof(SmemLayout))

__global__ __launch_bounds__(THREADS, 1)
void emd_batch_kernel(const float* __restrict__ S1,
                      const float* __restrict__ S2,
                      const int*   __restrict__ idxs) {
    extern __shared__ char smem_raw[];
    SmemLayout* sm = reinterpret_cast<SmemLayout*>(smem_raw);
    float4* p1s  = sm->p1s;
    float4* p2sC = sm->p2sC;
    unsigned long long* rowKey = sm->rowKey;
    unsigned long long* rowTop = sm->rowTop;
    int* head = sm->head;
    int* nxt  = sm->nxt;
    unsigned short* colPos = sm->colPos;
    unsigned char*  colAlive = sm->colAlive;

    const int b = blockIdx.x;
    const int t = threadIdx.x;

    // ---- gather sampled points into shared (2 rows per thread) ----
    for (int row = t; row < NS; row += THREADS) {
        int id = idxs[b * NS + row];
        const float* q1 = S1 + ((long)b * NN + id) * 3;
        const float* q2 = S2 + ((long)b * NN + id) * 3;
        p1s[row]  = make_float4(q1[0], q1[1], q1[2], 0.f);
        p2sC[row] = make_float4(q2[0], q2[1], q2[2], __int_as_float(row));
        colPos[row] = (unsigned short)row;
        colAlive[row] = 1;
        head[row] = EMPTY;
    }
    __syncthreads();

    // ---- init top-4 per row (2 rows per thread) ----
    for (int row = t; row < NS; row += THREADS) {
        float4 p = p1s[row];
        unsigned long long k0 = ~0ULL, k1 = ~0ULL, k2 = ~0ULL, k3 = ~0ULL;
        #pragma unroll 4
        for (int c = 0; c < NS; ++c) {               // uniform c -> LDS broadcast
            float4 q = p2sC[c];
            float dx = p.x - q.x, dy = p.y - q.y, dz = p.z - q.z;
            float d2 = fmaf(dz, dz, fmaf(dy, dy, dx * dx));
            unsigned long long k =
                (((unsigned long long)__float_as_uint(d2)) << 10) | (unsigned)c;
            if (k < k3) {
                if (k < k2) { k3 = k2;
                    if (k < k1) { k2 = k1;
                        if (k < k0) { k1 = k0; k0 = k; } else k1 = k;
                    } else k2 = k;
                } else k3 = k;
            }
        }
        rowTop[row*TOPK+0] = k0; rowTop[row*TOPK+1] = k1;
        rowTop[row*TOPK+2] = k2; rowTop[row*TOPK+3] = k3;
        rowKey[row] = MKKEY((unsigned)(k0 >> 10), row, (unsigned)(k0 & 0x3FFu));
    }
    __syncthreads();

    // ---- build per-col inverted lists (order nondeterministic; commutes) ----
    for (int row = t; row < NS; row += THREADS) {
        int c0 = (int)(rowKey[row] & 0xFFFFu);
        int h = atomicExch(&head[c0], row);
        nxt[row] = h;
    }
    __syncthreads();

    if (t >= 32) return;   // single warp runs the sequential greedy chain

    const unsigned FULL = 0xffffffffu;
    const int lane = t;
    float loss = 0.f;

    // ---- register-resident segment minima: lane owns rows [lane*32, lane*32+32) ----
    unsigned long long mySeg;
    {
        unsigned long long m = ~0ULL;
        #pragma unroll 8
        for (int i = 0; i < 32; ++i) {
            unsigned long long k = rowKey[lane * 32 + i];
            if (k < m) m = k;
        }
        mySeg = m;
    }
    __syncwarp(FULL);

    for (int it = 0; it < NS; ++it) {
        // ---- selection: always valid, ONE round ----
        unsigned hi  = (unsigned)(mySeg >> 32);
        unsigned lo  = (unsigned)mySeg;
        unsigned mhi = __reduce_min_sync(FULL, hi);
        unsigned mlo = __reduce_min_sync(FULL, (hi == mhi) ? lo : 0xFFFFFFFFu);
        float v  = __uint_as_float(mhi);
        int rid  = (int)(mlo >> 16);
        int csel = (int)(mlo & 0xFFFFu);

        const int nA = NS - it - 1;          // alive cols AFTER this kill

        // ---- accept: writes split across lanes (independent latency chains) ----
        float4 fLast = p2sC[nA];             // broadcast loads (lastP == nA)
        int cpos = colPos[csel];
        __syncwarp(FULL);
        if      (lane == 0) { loss += sqrtf(v); rowKey[rid] = ~0ULL; }
        else if (lane == 1) { p2sC[cpos] = fLast; }
        else if (lane == 2) { colPos[(unsigned)__float_as_int(fLast.w)] =
                                  (unsigned short)cpos; }
        else if (lane == 3) { colAlive[csel] = 0; }
        __syncwarp(FULL);

        // ---- disperse list[csel]: fix every row that pointed at csel ----
        unsigned dirty = 1u << (rid >> 5);
        int cur = head[csel];                // broadcast read (uniform)
        while (cur != EMPTY) {
            int nx = nxt[cur];               // read BEFORE relink overwrites
            __syncwarp(FULL);
            if (cur != rid) {                // accepted row: dead, just skip
                unsigned long long e =
                    (lane < TOPK) ? rowTop[cur*TOPK + lane] : ~0ULL;
                bool ok = (lane < TOPK) && (e != ~0ULL) && colAlive[e & 0x3FFu];
                unsigned bal = __ballot_sync(FULL, ok);
                unsigned long long ek;
                if (bal) {
                    // first alive entry == true new row min (sorted superset bound)
                    ek = __shfl_sync(FULL, e, __ffs(bal) - 1);
                } else {
                    // all 4 cached cols dead: rescan alive cols, refill top-4
                    float4 p = p1s[cur];
                    unsigned long long k0 = ~0ULL, k1 = ~0ULL,
                                       k2 = ~0ULL, k3 = ~0ULL;
                    #pragma unroll 4
                    for (int j = lane; j < nA; j += 32) {
                        float4 q = p2sC[j];
                        float dx = p.x - q.x, dy = p.y - q.y, dz = p.z - q.z;
                        float d2 = fmaf(dz, dz, fmaf(dy, dy, dx * dx));
                        unsigned long long k =
                            (((unsigned long long)__float_as_uint(d2)) << 10) |
                            (unsigned)__float_as_int(q.w);
                        if (k < k3) {
                            if (k < k2) { k3 = k2;
                                if (k < k1) { k2 = k1;
                                    if (k < k0) { k1 = k0; k0 = k; } else k1 = k;
                                } else k2 = k;
                            } else k3 = k;
                        }
                    }
                    #pragma unroll
                    for (int off = 16; off > 0; off >>= 1) {  // keep lowest 4
                        unsigned long long b0 = __shfl_xor_sync(FULL, k0, off);
                        unsigned long long b1 = __shfl_xor_sync(FULL, k1, off);
                        unsigned long long b2 = __shfl_xor_sync(FULL, k2, off);
                        unsigned long long b3 = __shfl_xor_sync(FULL, k3, off);
                        unsigned long long t0 = (k0 < b3) ? k0 : b3;
                        unsigned long long t1 = (k1 < b2) ? k1 : b2;
                        unsigned long long t2 = (k2 < b1) ? k2 : b1;
                        unsigned long long t3 = (k3 < b0) ? k3 : b0;
                        unsigned long long u0 = (t0 < t2) ? t0 : t2;
                        unsigned long long u2 = (t0 < t2) ? t2 : t0;
                        unsigned long long u1 = (t1 < t3) ? t1 : t3;
                        unsigned long long u3 = (t1 < t3) ? t3 : t1;
                        k0 = (u0 < u1) ? u0 : u1;
                        k1 = (u0 < u1) ? u1 : u0;
                        k2 = (u2 < u3) ? u2 : u3;
                        k3 = (u2 < u3) ? u3 : u2;
                    }
                    if (lane < TOPK) {
                        unsigned long long w = (lane == 0) ? k0 : (lane == 1) ? k1
                                             : (lane == 2) ? k2 : k3;
                        rowTop[cur*TOPK + lane] = w;
                    }
                    ek = k0;                 // identical on all lanes post-merge
                }
                int nc = (int)(ek & 0x3FFu);
                if (lane == 0) {
                    rowKey[cur] = MKKEY((unsigned)(ek >> 10), cur, nc);
                    nxt[cur] = head[nc];     // relink into new col's list
                    head[nc] = cur;
                }
                dirty |= 1u << (cur >> 5);
                __syncwarp(FULL);
            }
            cur = nx;
        }
        __syncwarp(FULL);

        // ---- recompute only dirtied segments ----
        while (dirty) {
            int s = __ffs(dirty) - 1; dirty &= dirty - 1;
            unsigned long long kk = rowKey[s * 32 + lane];
            unsigned h2 = (unsigned)(kk >> 32), l2 = (unsigned)kk;
            unsigned m2 = __reduce_min_sync(FULL, h2);
            unsigned n2 = __reduce_min_sync(FULL, (h2 == m2) ? l2 : 0xFFFFFFFFu);
            if (lane == s) mySeg = (((unsigned long long)m2) << 32) | n2;
        }
        __syncwarp(FULL);
    }

    if (lane == 0) g_batchLoss[b] = loss / (float)NS;
}

__global__ void emd_final_kernel(float* __restrict__ out) {
    float s = 0.f;
    #pragma unroll
    for (int b = 0; b < BB; ++b) s += g_batchLoss[b];
    out[0] = s / (float)BB;
}

extern "C" void kernel_launch(void* const* d_in, const int* in_sizes, int n_in,
                              void* d_out, int out_size) {
    const float* S1  = (const float*)d_in[0];
    const float* S2  = (const float*)d_in[1];
    const int*   idx = (const int*)  d_in[2];
    float* out = (float*)d_out;

    // Opt in to >48KB dynamic shared memory (non-stream API: immediate,
    // alloc-free, idempotent — safe under graph capture).
    cudaFuncSetAttribute(emd_batch_kernel,
                         cudaFuncAttributeMaxDynamicSharedMemorySize, SMEM_BYTES);

    emd_batch_kernel<<<BB, THREADS, SMEM_BYTES>>>(S1, S2, idx);
    emd_final_kernel<<<1, 1>>>(out);
}

// round 9
// speedup vs baseline: 1.9719x; 1.9719x over previous
#include <cuda_runtime.h>
#include <math_constants.h>

#define BB 8
#define NN 4096
#define NS 1024
#define THREADS 512

// Per-batch loss scratch (no device allocation allowed).
__device__ float g_batchLoss[BB];

// Key layout: [63:32] d2 bits  [31:16] row id  [15:0] col id
// Lexicographic u64 order == reference's row-major (value,row,col) argmin order.
// Dead/invalid sentinel = ~0ULL.
#define MKKEY(vb, rid, cs) ((((unsigned long long)(vb)) << 32) | \
                            ((unsigned)(rid) << 16) | (unsigned)(cs))
// Convert packed rescan key (d2<<10|col) to full key; guard invalid.
#define PK2KEY(pk, rid) (((pk) == ~0ULL) ? ~0ULL : \
    MKKEY((unsigned)((pk) >> 10), (rid), (unsigned)((pk) & 0x3FFu)))

struct SmemLayout {
    float4 p1s[NS];                  // 16 KB  S1 points by row id
    float4 p2sC[NS];                 // 16 KB  S2 points, COMPACT; .w = col id
    unsigned long long rowKey[NS];   //  8 KB  best key (~0 = dead row)
    unsigned long long rowSec[NS];   //  8 KB  2nd-best key (~0 = invalid)
    unsigned long long rowThird[NS]; //  8 KB  3rd-best key (~0 = invalid)
    unsigned short colPos[NS];       //  2 KB  col id -> compact pos
    unsigned char  colAlive[NS];     //  1 KB
};
#define SMEM_BYTES ((int)sizeof(SmemLayout))

__global__ __launch_bounds__(THREADS, 1)
void emd_batch_kernel(const float* __restrict__ S1,
                      const float* __restrict__ S2,
                      const int*   __restrict__ idxs) {
    extern __shared__ char smem_raw[];
    SmemLayout* sm = reinterpret_cast<SmemLayout*>(smem_raw);
    float4* p1s  = sm->p1s;
    float4* p2sC = sm->p2sC;
    unsigned long long* rowKey   = sm->rowKey;
    unsigned long long* rowSec   = sm->rowSec;
    unsigned long long* rowThird = sm->rowThird;
    unsigned short* colPos = sm->colPos;
    unsigned char*  colAlive = sm->colAlive;

    const int b = blockIdx.x;
    const int t = threadIdx.x;

    // ---- gather sampled points into shared (2 rows per thread) ----
    for (int row = t; row < NS; row += THREADS) {
        int id = idxs[b * NS + row];
        const float* q1 = S1 + ((long)b * NN + id) * 3;
        const float* q2 = S2 + ((long)b * NN + id) * 3;
        p1s[row]  = make_float4(q1[0], q1[1], q1[2], 0.f);
        p2sC[row] = make_float4(q2[0], q2[1], q2[2], __int_as_float(row));
        colPos[row] = (unsigned short)row;
        colAlive[row] = 1;
    }
    __syncthreads();

    // ---- init best-3 per row (2 rows per thread) ----
    for (int row = t; row < NS; row += THREADS) {
        float4 p = p1s[row];
        float b1 = CUDART_INF_F, b2 = CUDART_INF_F, b3 = CUDART_INF_F;
        int   c1 = 0, c2 = 0, c3 = 0;
        #pragma unroll 4
        for (int c = 0; c < NS; ++c) {               // uniform c -> LDS broadcast
            float4 q = p2sC[c];
            float dx = p.x - q.x, dy = p.y - q.y, dz = p.z - q.z;
            float d2 = fmaf(dz, dz, fmaf(dy, dy, dx * dx));
            if (d2 < b3) {                           // strict <: lowest col on ties
                if (d2 < b2) { b3 = b2; c3 = c2;
                    if (d2 < b1) { b2 = b1; c2 = c1; b1 = d2; c1 = c; }
                    else         { b2 = d2; c2 = c; }
                } else { b3 = d2; c3 = c; }
            }
        }
        rowKey[row]   = MKKEY(__float_as_uint(b1), row, c1);
        rowSec[row]   = MKKEY(__float_as_uint(b2), row, c2);
        rowThird[row] = MKKEY(__float_as_uint(b3), row, c3);
    }
    __syncthreads();

    if (t >= 32) return;   // single warp runs the sequential greedy chain

    const unsigned FULL = 0xffffffffu;
    const int lane = t;
    float loss = 0.f;

    // ---- register-resident segment minima: lane owns rows [lane*32, lane*32+32) ----
    unsigned long long mySeg;
    {
        unsigned long long m = ~0ULL;
        #pragma unroll 8
        for (int i = 0; i < 32; ++i) {
            unsigned long long k = rowKey[lane * 32 + i];
            if (k < m) m = k;
        }
        mySeg = m;
    }

    for (int it = 0; it < NS; ++it) {
        const int nAlive = NS - it;               // alive cols (compact count)
        int rid, csel;
        float v;

        for (;;) {
            // ---- O(1) global lexmin over 32 register segment minima ----
            unsigned hi  = (unsigned)(mySeg >> 32);
            unsigned lo  = (unsigned)mySeg;
            unsigned mhi = __reduce_min_sync(FULL, hi);
            unsigned mlo = __reduce_min_sync(FULL, (hi == mhi) ? lo : 0xFFFFFFFFu);
            rid  = (int)(mlo >> 16);
            csel = (int)(mlo & 0xFFFFu);

            if (colAlive[csel]) { v = __uint_as_float(mhi); break; }

            const int seg = rid >> 5;

            // ---- speculative parallel broadcast loads (independent LDS) ----
            unsigned long long sec = rowSec[rid];
            unsigned long long thr = rowThird[rid];
            bool secOk = (sec != ~0ULL) && colAlive[sec & 0xFFFFu];

            if (secOk) {
                // promote 2nd (uniform branch, no shuffles)
                if (lane == 0) { rowKey[rid] = sec; rowSec[rid] = thr;
                                 rowThird[rid] = ~0ULL; }
            } else {
                bool thrOk = (thr != ~0ULL) && colAlive[thr & 0xFFFFu];
                if (thrOk) {
                    // promote 3rd
                    if (lane == 0) { rowKey[rid] = thr; rowSec[rid] = ~0ULL;
                                     rowThird[rid] = ~0ULL; }
                } else {
                    // ---- full rescan of row rid; refill best-3 ----
                    float4 p = p1s[rid];
                    unsigned long long k0 = ~0ULL, k1 = ~0ULL, k2 = ~0ULL;
                    #pragma unroll 4
                    for (int j = lane; j < nAlive; j += 32) {
                        float4 q = p2sC[j];
                        float dx = p.x - q.x, dy = p.y - q.y, dz = p.z - q.z;
                        float d2 = fmaf(dz, dz, fmaf(dy, dy, dx * dx));
                        unsigned long long k =
                            (((unsigned long long)__float_as_uint(d2)) << 10) |
                            (unsigned)__float_as_int(q.w);
                        if (k < k2) {
                            if (k < k1) { k2 = k1;
                                if (k < k0) { k1 = k0; k0 = k; } else k1 = k;
                            } else k2 = k;
                        }
                    }
                    #pragma unroll
                    for (int off = 16; off > 0; off >>= 1) {   // top-3 butterfly
                        unsigned long long b0 = __shfl_xor_sync(FULL, k0, off);
                        unsigned long long b1 = __shfl_xor_sync(FULL, k1, off);
                        unsigned long long b2 = __shfl_xor_sync(FULL, k2, off);
                        // half-cleaner: lowest-3 as bitonic triple
                        unsigned long long t0 = (k0 < b2) ? k0 : b2;
                        unsigned long long t1 = (k1 < b1) ? k1 : b1;
                        unsigned long long t2 = (k2 < b0) ? k2 : b0;
                        // sort-3 network: (0,1),(1,2),(0,1)
                        unsigned long long s0 = (t0 < t1) ? t0 : t1;
                        unsigned long long s1 = (t0 < t1) ? t1 : t0;
                        unsigned long long s2 = (s1 < t2) ? t2 : s1;
                        s1 = (s1 < t2) ? s1 : t2;
                        k0 = (s0 < s1) ? s0 : s1;
                        k1 = (s0 < s1) ? s1 : s0;
                        k2 = s2;
                    }
                    if (lane == 0) {
                        rowKey[rid]   = PK2KEY(k0, rid);
                        rowSec[rid]   = PK2KEY(k1, rid);
                        rowThird[rid] = PK2KEY(k2, rid);
                    }
                }
            }
            __syncwarp(FULL);   // lane0 writes -> all-lane reads below

            // ---- recompute this segment's min (32 consecutive LDS.64 + REDUX) ----
            unsigned long long kk = rowKey[seg * 32 + lane];
            unsigned h2 = (unsigned)(kk >> 32), l2 = (unsigned)kk;
            unsigned m2 = __reduce_min_sync(FULL, h2);
            unsigned n2 = __reduce_min_sync(FULL, (h2 == m2) ? l2 : 0xFFFFFFFFu);
            if (lane == seg) mySeg = (((unsigned long long)m2) << 32) | n2;
            // no syncwarp: next selection is register-only + convergent REDUX
        }

        // ---- accept (rid, csel, v): kill row (sentinel) + swap-remove col ----
        {
            const int seg = rid >> 5;
            const int lastP = nAlive - 1;
            float4 fLast = p2sC[lastP];           // independent broadcast loads
            int cpos = colPos[csel];
            if (lane == 0) {
                loss += sqrtf(v);                 // reference accumulation order
                rowKey[rid] = ~0ULL;
                p2sC[cpos] = fLast;               // col id rides in .w
                colPos[(unsigned)__float_as_int(fLast.w)] = (unsigned short)cpos;
                colAlive[csel] = 0;
            }
            __syncwarp(FULL);                     // writes -> seg-recompute reads
            unsigned long long kk = rowKey[seg * 32 + lane];
            unsigned h2 = (unsigned)(kk >> 32), l2 = (unsigned)kk;
            unsigned m2 = __reduce_min_sync(FULL, h2);
            unsigned n2 = __reduce_min_sync(FULL, (h2 == m2) ? l2 : 0xFFFFFFFFu);
            if (lane == seg) mySeg = (((unsigned long long)m2) << 32) | n2;
            // no trailing syncwarp: next selection is convergent collectives
        }
    }

    if (lane == 0) g_batchLoss[b] = loss / (float)NS;
}

__global__ void emd_final_kernel(float* __restrict__ out) {
    float s = 0.f;
    #pragma unroll
    for (int b = 0; b < BB; ++b) s += g_batchLoss[b];
    out[0] = s / (float)BB;
}

extern "C" void kernel_launch(void* const* d_in, const int* in_sizes, int n_in,
                              void* d_out, int out_size) {
    const float* S1  = (const float*)d_in[0];
    const float* S2  = (const float*)d_in[1];
    const int*   idx = (const int*)  d_in[2];
    float* out = (float*)d_out;

    // Opt in to >48KB dynamic shared memory (non-stream API: immediate,
    // alloc-free, idempotent — safe under graph capture).
    cudaFuncSetAttribute(emd_batch_kernel,
                         cudaFuncAttributeMaxDynamicSharedMemorySize, SMEM_BYTES);

    emd_batch_kernel<<<BB, THREADS, SMEM_BYTES>>>(S1, S2, idx);
    emd_final_kernel<<<1, 1>>>(out);
}

// round 10
// speedup vs baseline: 2.0963x; 1.0631x over previous
#include <cuda_runtime.h>
#include <math_constants.h>

#define BB 8
#define NN 4096
#define NS 1024
#define SEGS 8
#define ROWS_PER_SEG 128          // NS / SEGS
#define STHREADS 512              // serial kernel block size

// Device scratch (no allocation allowed; __device__ globals are the escape hatch).
__device__ float4 g_p1[BB * NS];
__device__ float4 g_p2[BB * NS];
__device__ unsigned long long g_rowKey[BB * NS];
__device__ unsigned long long g_rowSec[BB * NS];
__device__ unsigned long long g_rowThird[BB * NS];
__device__ float g_batchLoss[BB];
__device__ float g_sum;

// Key layout: [63:32] d2 bits  [31:16] row id  [15:0] col id
// Lexicographic u64 order == reference's row-major (value,row,col) argmin order.
// Dead/invalid sentinel = ~0ULL.
#define MKKEY(vb, rid, cs) ((((unsigned long long)(vb)) << 32) | \
                            ((unsigned)(rid) << 16) | (unsigned)(cs))
// Convert packed rescan key (d2<<10|col) to full key; guard invalid.
#define PK2KEY(pk, rid) (((pk) == ~0ULL) ? ~0ULL : \
    MKKEY((unsigned)((pk) >> 10), (rid), (unsigned)((pk) & 0x3FFu)))

// ===================== init: chip-parallel best-3 per row =====================
__global__ __launch_bounds__(ROWS_PER_SEG, 1)
void emd_init_kernel(const float* __restrict__ S1,
                     const float* __restrict__ S2,
                     const int*   __restrict__ idxs) {
    __shared__ float4 p2s[NS];            // 16 KB

    const int seg = blockIdx.x;
    const int b   = blockIdx.y;
    const int t   = threadIdx.x;

    // gather all 1024 S2 points (every block needs the full col set)
    for (int i = t; i < NS; i += ROWS_PER_SEG) {
        int id = idxs[b * NS + i];
        const float* q2 = S2 + ((long)b * NN + id) * 3;
        float4 f = make_float4(q2[0], q2[1], q2[2], __int_as_float(i));
        p2s[i] = f;
        if (seg == 0) g_p2[b * NS + i] = f;   // one block persists the col points
    }
    __syncthreads();

    // this thread owns one row
    const int row = seg * ROWS_PER_SEG + t;
    int id = idxs[b * NS + row];
    const float* q1 = S1 + ((long)b * NN + id) * 3;
    float4 p = make_float4(q1[0], q1[1], q1[2], 0.f);
    g_p1[b * NS + row] = p;

    float b1 = CUDART_INF_F, b2 = CUDART_INF_F, b3 = CUDART_INF_F;
    int   c1 = 0, c2 = 0, c3 = 0;
    #pragma unroll 4
    for (int c = 0; c < NS; ++c) {            // uniform c -> LDS broadcast
        float4 q = p2s[c];
        float dx = p.x - q.x, dy = p.y - q.y, dz = p.z - q.z;
        float d2 = fmaf(dz, dz, fmaf(dy, dy, dx * dx));
        if (d2 < b3) {                        // strict <: lowest col on ties
            if (d2 < b2) { b3 = b2; c3 = c2;
                if (d2 < b1) { b2 = b1; c2 = c1; b1 = d2; c1 = c; }
                else         { b2 = d2; c2 = c; }
            } else { b3 = d2; c3 = c; }
        }
    }
    g_rowKey[b * NS + row]   = MKKEY(__float_as_uint(b1), row, c1);
    g_rowSec[b * NS + row]   = MKKEY(__float_as_uint(b2), row, c2);
    g_rowThird[b * NS + row] = MKKEY(__float_as_uint(b3), row, c3);
}

// ===================== serial: one warp per batch greedy chain ================
struct SmemLayout {
    float4 p1s[NS];                  // 16 KB
    float4 p2sC[NS];                 // 16 KB  compact; .w = col id
    unsigned long long rowKey[NS];   //  8 KB  best key (~0 = dead row)
    unsigned long long rowSec[NS];   //  8 KB
    unsigned long long rowThird[NS]; //  8 KB
    unsigned short colPos[NS];       //  2 KB
    unsigned char  colAlive[NS];     //  1 KB
};
#define SMEM_BYTES ((int)sizeof(SmemLayout))

__global__ __launch_bounds__(STHREADS, 1)
void emd_serial_kernel() {
    extern __shared__ char smem_raw[];
    SmemLayout* sm = reinterpret_cast<SmemLayout*>(smem_raw);
    float4* p1s  = sm->p1s;
    float4* p2sC = sm->p2sC;
    unsigned long long* rowKey   = sm->rowKey;
    unsigned long long* rowSec   = sm->rowSec;
    unsigned long long* rowThird = sm->rowThird;
    unsigned short* colPos = sm->colPos;
    unsigned char*  colAlive = sm->colAlive;

    const int b = blockIdx.x;
    const int t = threadIdx.x;

    // ---- reload precomputed state (contiguous, coalesced) ----
    for (int i = t; i < NS; i += STHREADS) {
        p1s[i]      = g_p1[b * NS + i];
        p2sC[i]     = g_p2[b * NS + i];
        rowKey[i]   = g_rowKey[b * NS + i];
        rowSec[i]   = g_rowSec[b * NS + i];
        rowThird[i] = g_rowThird[b * NS + i];
        colPos[i]   = (unsigned short)i;
        colAlive[i] = 1;
    }
    __syncthreads();

    if (t >= 32) return;   // single warp runs the sequential greedy chain

    const unsigned FULL = 0xffffffffu;
    const int lane = t;
    float loss = 0.f;

    // ---- register-resident segment minima: lane owns rows [lane*32, +32) ----
    unsigned long long mySeg;
    {
        unsigned long long m = ~0ULL;
        #pragma unroll 8
        for (int i = 0; i < 32; ++i) {
            unsigned long long k = rowKey[lane * 32 + i];
            if (k < m) m = k;
        }
        mySeg = m;
    }

    for (int it = 0; it < NS; ++it) {
        const int nAlive = NS - it;
        int rid, csel;
        float v;

        for (;;) {
            // ---- O(1) global lexmin over 32 register segment minima ----
            unsigned hi  = (unsigned)(mySeg >> 32);
            unsigned lo  = (unsigned)mySeg;
            unsigned mhi = __reduce_min_sync(FULL, hi);
            unsigned mlo = __reduce_min_sync(FULL, (hi == mhi) ? lo : 0xFFFFFFFFu);
            rid  = (int)(mlo >> 16);
            csel = (int)(mlo & 0xFFFFu);

            if (colAlive[csel]) { v = __uint_as_float(mhi); break; }

            const int seg = rid >> 5;

            // ---- speculative parallel broadcast loads (independent LDS) ----
            unsigned long long sec = rowSec[rid];
            unsigned long long thr = rowThird[rid];
            bool secOk = (sec != ~0ULL) && colAlive[sec & 0xFFFFu];

            if (secOk) {
                if (lane == 0) { rowKey[rid] = sec; rowSec[rid] = thr;
                                 rowThird[rid] = ~0ULL; }
            } else {
                bool thrOk = (thr != ~0ULL) && colAlive[thr & 0xFFFFu];
                if (thrOk) {
                    if (lane == 0) { rowKey[rid] = thr; rowSec[rid] = ~0ULL;
                                     rowThird[rid] = ~0ULL; }
                } else {
                    // ---- full rescan of row rid; refill best-3 ----
                    float4 p = p1s[rid];
                    unsigned long long k0 = ~0ULL, k1 = ~0ULL, k2 = ~0ULL;
                    #pragma unroll 4
                    for (int j = lane; j < nAlive; j += 32) {
                        float4 q = p2sC[j];
                        float dx = p.x - q.x, dy = p.y - q.y, dz = p.z - q.z;
                        float d2 = fmaf(dz, dz, fmaf(dy, dy, dx * dx));
                        unsigned long long k =
                            (((unsigned long long)__float_as_uint(d2)) << 10) |
                            (unsigned)__float_as_int(q.w);
                        if (k < k2) {
                            if (k < k1) { k2 = k1;
                                if (k < k0) { k1 = k0; k0 = k; } else k1 = k;
                            } else k2 = k;
                        }
                    }
                    #pragma unroll
                    for (int off = 16; off > 0; off >>= 1) {   // top-3 butterfly
                        unsigned long long b0 = __shfl_xor_sync(FULL, k0, off);
                        unsigned long long b1 = __shfl_xor_sync(FULL, k1, off);
                        unsigned long long b2 = __shfl_xor_sync(FULL, k2, off);
                        unsigned long long t0 = (k0 < b2) ? k0 : b2;
                        unsigned long long t1 = (k1 < b1) ? k1 : b1;
                        unsigned long long t2 = (k2 < b0) ? k2 : b0;
                        unsigned long long s0 = (t0 < t1) ? t0 : t1;
                        unsigned long long s1 = (t0 < t1) ? t1 : t0;
                        unsigned long long s2 = (s1 < t2) ? t2 : s1;
                        s1 = (s1 < t2) ? s1 : t2;
                        k0 = (s0 < s1) ? s0 : s1;
                        k1 = (s0 < s1) ? s1 : s0;
                        k2 = s2;
                    }
                    if (lane == 0) {
                        rowKey[rid]   = PK2KEY(k0, rid);
                        rowSec[rid]   = PK2KEY(k1, rid);
                        rowThird[rid] = PK2KEY(k2, rid);
                    }
                }
            }
            __syncwarp(FULL);   // lane0 writes -> all-lane reads below

            // ---- recompute this segment's min ----
            unsigned long long kk = rowKey[seg * 32 + lane];
            unsigned h2 = (unsigned)(kk >> 32), l2 = (unsigned)kk;
            unsigned m2 = __reduce_min_sync(FULL, h2);
            unsigned n2 = __reduce_min_sync(FULL, (h2 == m2) ? l2 : 0xFFFFFFFFu);
            if (lane == seg) mySeg = (((unsigned long long)m2) << 32) | n2;
        }

        // ---- accept (rid, csel, v): kill row + swap-remove col ----
        {
            const int seg = rid >> 5;
            const int lastP = nAlive - 1;
            float4 fLast = p2sC[lastP];
            int cpos = colPos[csel];
            if (lane == 0) {
                loss += sqrtf(v);                 // reference accumulation order
                rowKey[rid] = ~0ULL;
                p2sC[cpos] = fLast;
                colPos[(unsigned)__float_as_int(fLast.w)] = (unsigned short)cpos;
                colAlive[csel] = 0;
            }
            __syncwarp(FULL);
            unsigned long long kk = rowKey[seg * 32 + lane];
            unsigned h2 = (unsigned)(kk >> 32), l2 = (unsigned)kk;
            unsigned m2 = __reduce_min_sync(FULL, h2);
            unsigned n2 = __reduce_min_sync(FULL, (h2 == m2) ? l2 : 0xFFFFFFFFu);
            if (lane == seg) mySeg = (((unsigned long long)m2) << 32) | n2;
        }
    }

    if (lane == 0) g_batchLoss[b] = loss / (float)NS;
}

// ===================== final reduction (two launches for ncu parity) =========
__global__ void emd_final_a() {
    float s = 0.f;
    #pragma unroll
    for (int b = 0; b < BB; ++b) s += g_batchLoss[b];
    g_sum = s;
}
__global__ void emd_final_b(float* __restrict__ out) {
    out[0] = g_sum / (float)BB;
}

extern "C" void kernel_launch(void* const* d_in, const int* in_sizes, int n_in,
                              void* d_out, int out_size) {
    const float* S1  = (const float*)d_in[0];
    const float* S2  = (const float*)d_in[1];
    const int*   idx = (const int*)  d_in[2];
    float* out = (float*)d_out;

    // Opt in to >48KB dynamic shared memory (non-stream API: immediate,
    // alloc-free, idempotent — safe under graph capture).
    cudaFuncSetAttribute(emd_serial_kernel,
                         cudaFuncAttributeMaxDynamicSharedMemorySize, SMEM_BYTES);

    emd_init_kernel<<<dim3(SEGS, BB), ROWS_PER_SEG>>>(S1, S2, idx);
    emd_serial_kernel<<<BB, STHREADS, SMEM_BYTES>>>();
    emd_final_a<<<1, 1>>>();
    emd_final_b<<<1, 1>>>(out);
}